// round 1
// baseline (speedup 1.0000x reference)
#include <cuda_runtime.h>
#include <math.h>

#define HWC   65536
#define Bc    8
#define Ec    64
#define Kc    8
#define Sc    4
#define CHUNKS 37            // chunks per image; 8*37 = 296 blocks = 2 per SM on 148 SMs
#define PIXPC  1776          // ceil(65536/37) rounded up to multiple of 16
#define TEMPc  0.2f
#define EPSF   1e-8f

// Scratch (no allocations allowed): per-(b,k) sums over pixels, and counts.
__device__ float g_sum[Bc * Kc * Ec];
__device__ float g_cnt[Bc * Kc];

// ---------------------------------------------------------------------------
// Kernel 0: zero the accumulators (graph replays need fresh state every call)
// ---------------------------------------------------------------------------
__global__ void zero_kernel() {
    int t = threadIdx.x;
    for (int i = t; i < Bc * Kc * Ec; i += blockDim.x) g_sum[i] = 0.0f;
    if (t < Bc * Kc) g_cnt[t] = 0.0f;
}

// ---------------------------------------------------------------------------
// Kernel 1: class-conditional sums + counts.
//   Phase A (thread<->pixel, coalesced): derive label k per pixel from the
//   one-hot masks into shared memory; counts via warp ballots.
//   Phase B (thread = (e, group)): each thread owns one embedding channel e
//   and a 4-pixel-stride lane; reads float4 of 4 consecutive pixels from
//   global (warp = 8 rows x 64B contiguous -> fully sectored), accumulates
//   into 8 per-class registers with predicated adds, flushes once per block
//   via shfl + atomicAdd.
// ---------------------------------------------------------------------------
__global__ __launch_bounds__(256, 2) void sums_kernel(
    const float* __restrict__ emb,    // [B,E,HW]
    const float* __restrict__ masks)  // [B,K,HW]
{
    __shared__ __align__(16) unsigned char sk[1792];  // labels for this chunk (7*256)

    const int tid   = threadIdx.x;
    const int blk   = blockIdx.x;
    const int b     = blk / CHUNKS;
    const int chunk = blk % CHUNKS;
    const int n0    = chunk * PIXPC;

    // ---- Phase A: labels + counts -------------------------------------
    unsigned cnt[Kc];
#pragma unroll
    for (int j = 0; j < Kc; ++j) cnt[j] = 0u;

    const float* mbase = masks + (size_t)b * Kc * HWC;
#pragma unroll
    for (int it = 0; it < 7; ++it) {            // 7*256 = 1792 slots
        int p = it * 256 + tid;
        int n = n0 + p;
        int k = 255;
        if (p < PIXPC && n < HWC) {
            k = 0;
#pragma unroll
            for (int j = 0; j < Kc; ++j) {
                if (mbase[(size_t)j * HWC + n] > 0.5f) k = j;
            }
        }
#pragma unroll
        for (int j = 0; j < Kc; ++j)
            cnt[j] += __popc(__ballot_sync(0xffffffffu, k == j));
        sk[p] = (unsigned char)k;
    }
    if ((tid & 31) == 0) {
#pragma unroll
        for (int j = 0; j < Kc; ++j)
            atomicAdd(&g_cnt[b * Kc + j], (float)cnt[j]);
    }
    __syncthreads();

    // ---- Phase B: channel-sliced accumulation -------------------------
    const int e = tid >> 2;     // 0..63
    const int g = tid & 3;      // 0..3

    const float* ebase = emb + ((size_t)b * Ec + e) * HWC + n0 + g * 4;

    float acc[Kc];
#pragma unroll
    for (int j = 0; j < Kc; ++j) acc[j] = 0.0f;

    int nvalid = (HWC - n0) / 16;              // fully-valid 16-pixel iterations
    if (nvalid > PIXPC / 16) nvalid = PIXPC / 16;   // = 111 for full chunks

#pragma unroll 4
    for (int i = 0; i < nvalid; ++i) {
        float4 v = *(const float4*)(ebase + i * 16);
        unsigned kk = *(const unsigned*)(sk + i * 16 + g * 4);
#pragma unroll
        for (int px = 0; px < 4; ++px) {
            int k = (kk >> (8 * px)) & 255;
            float val = (px == 0) ? v.x : (px == 1) ? v.y : (px == 2) ? v.z : v.w;
#pragma unroll
            for (int j = 0; j < Kc; ++j) {
                if (k == j) acc[j] += val;
            }
        }
    }

    // reduce over the 4 g-lanes (adjacent lanes), flush to global
#pragma unroll
    for (int j = 0; j < Kc; ++j) {
        float v = acc[j];
        v += __shfl_xor_sync(0xffffffffu, v, 1);
        v += __shfl_xor_sync(0xffffffffu, v, 2);
        if (g == 0) atomicAdd(&g_sum[(b * Kc + j) * Ec + e], v);
    }
}

// ---------------------------------------------------------------------------
// Kernel 2: contrastive loss over all 256 (b,k,s) terms. One block.
// ---------------------------------------------------------------------------
__global__ __launch_bounds__(256, 1) void loss_kernel(
    const float* __restrict__ emb,   // [B,E,HW]
    const int*   __restrict__ pos,   // [B,K,S]
    float*       __restrict__ out)
{
    __shared__ float sm[Bc * Kc * Ec];   // class means
    __shared__ float snm[Bc * Kc];       // 1 / (max(||mean||,eps) * TEMP)
    __shared__ float red[256];

    const int t = threadIdx.x;

    // means = sums / max(count, 1)
    for (int i = t; i < Bc * Kc * Ec; i += 256) {
        int bk = i / Ec;
        sm[i] = g_sum[i] / fmaxf(g_cnt[bk], 1.0f);
    }
    __syncthreads();

    if (t < Bc * Kc) {
        float ss = 0.0f;
#pragma unroll
        for (int e = 0; e < Ec; ++e) {
            float v = sm[t * Ec + e];
            ss += v * v;
        }
        snm[t] = 1.0f / (fmaxf(sqrtf(ss), EPSF) * TEMPc);
    }
    __syncthreads();

    const int b = t >> 5;
    const int k = (t >> 2) & 7;
    const int s = t & 3;
    const int pix = pos[(b * Kc + k) * Sc + s];

    float z[Ec];
    float ss = 0.0f;
#pragma unroll
    for (int e = 0; e < Ec; ++e) {
        z[e] = emb[((size_t)b * Ec + e) * HWC + pix];
        ss += z[e] * z[e];
    }
    const float inz = 1.0f / fmaxf(sqrtf(ss), EPSF);

    float sims[Kc];
    float mx = -1e30f;
#pragma unroll
    for (int c = 0; c < Kc; ++c) {
        float d = 0.0f;
#pragma unroll
        for (int e = 0; e < Ec; ++e) d += z[e] * sm[(b * Kc + c) * Ec + e];
        sims[c] = d * inz * snm[b * Kc + c];
        mx = fmaxf(mx, sims[c]);
    }
    float se = 0.0f;
#pragma unroll
    for (int c = 0; c < Kc; ++c) se += expf(sims[c] - mx);
    const float term = (mx + logf(se)) - sims[k];

    red[t] = term;
    __syncthreads();
    for (int off = 128; off > 0; off >>= 1) {
        if (t < off) red[t] += red[t + off];
        __syncthreads();
    }
    if (t == 0) out[0] = red[0] * (1.0f / 256.0f);
}

// ---------------------------------------------------------------------------
extern "C" void kernel_launch(void* const* d_in, const int* in_sizes, int n_in,
                              void* d_out, int out_size)
{
    const float* emb   = (const float*)d_in[0];  // embeddings [8,64,256,256] f32
    const float* masks = (const float*)d_in[1];  // masks_onehot [8,8,256,256] f32
    const int*   pos   = (const int*)d_in[2];    // pos_pix [8,8,4] i32

    zero_kernel<<<1, 256>>>();
    sums_kernel<<<Bc * CHUNKS, 256>>>(emb, masks);
    loss_kernel<<<1, 256>>>(emb, pos, (float*)d_out);
}

// round 2
// speedup vs baseline: 1.6897x; 1.6897x over previous
#include <cuda_runtime.h>
#include <math.h>

#define HWC    65536
#define Bc     8
#define Ec     64
#define Kc     8
#define Sc     4
#define CHUNKS 37            // chunks per image; 8*37 = 296 blocks = 2/SM on 148 SMs
#define PIXPC  1776          // pixels per chunk (last chunk: 1600)
#define PHASE  896           // pixels staged per smem phase (2 phases per chunk)
#define PAIRSP 448           // pixel-pairs per phase
#define TEMPc  0.2f
#define EPSF   1e-8f

// Scratch: per-(b,k,e) sums and per-(b,k) counts. Zero at process start (static
// init) and re-zeroed by loss_kernel at the end of every call -> every
// kernel_launch (and every graph replay) starts from zeros. No zero kernel.
__device__ float g_sum[Bc * Kc * Ec];
__device__ float g_cnt[Bc * Kc];

// Packed fp32x2 helpers (Blackwell f32x2 path)
#define FFMA2(acc, m, v) \
    asm("fma.rn.f32x2 %0, %1, %2, %0;" : "+l"(acc) : "l"(m), "l"(v))
#define ADDX2(d, a, b) \
    asm("add.rn.f32x2 %0, %1, %2;" : "=l"(d) : "l"(a), "l"(b))
#define PACK2(d, lo, hi) \
    asm("mov.b64 %0, {%1, %2};" : "=l"(d) : "f"(lo), "f"(hi))
#define UNPACK2(lo, hi, s) \
    asm("mov.b64 {%0, %1}, %2;" : "=f"(lo), "=f"(hi) : "l"(s))

// ---------------------------------------------------------------------------
// Kernel 1: class-conditional sums + counts.
//   Per chunk, two phases. Phase A stages mask pixel-pairs (float2) for all 8
//   classes into smem and accumulates exact class counts. Phase B: thread =
//   (channel e, pixel-group g); float4 loads of 4 consecutive pixels; the
//   natural (px0,px1)/(px2,px3) register pairs feed packed fma.rn.f32x2
//   against the smem mask pairs -> 2 packed FFMA per class per 4 pixels.
// ---------------------------------------------------------------------------
__global__ __launch_bounds__(256, 2) void sums_kernel(
    const float* __restrict__ emb,    // [B,E,HW]
    const float* __restrict__ masks)  // [B,K,HW]
{
    __shared__ __align__(16) float2 sm_m[Kc * PAIRSP];   // 28,672 B

    const int tid   = threadIdx.x;
    const int blk   = blockIdx.x;
    const int b     = blk / CHUNKS;
    const int chunk = blk % CHUNKS;
    const int n0    = chunk * PIXPC;
    const int npix  = (HWC - n0 < PIXPC) ? (HWC - n0) : PIXPC;   // 1776 or 1600

    const int e = tid >> 2;     // 0..63  channel
    const int g = tid & 3;      // 0..3   pixel group

    unsigned long long acc[Kc];
#pragma unroll
    for (int j = 0; j < Kc; ++j) acc[j] = 0ull;

    float msum[Kc];
#pragma unroll
    for (int j = 0; j < Kc; ++j) msum[j] = 0.0f;

    const float* mb = masks + (size_t)b * Kc * HWC;

    for (int ph = 0; ph < 2; ++ph) {
        const int phoff = ph * PHASE;
        int npx = npix - phoff;
        if (npx <= 0) break;
        if (npx > PHASE) npx = PHASE;
        const int pairs = npx >> 1;     // 448 or 352 (both multiples of 8)
        const int iters = npx >> 4;     // 56 or 44

        if (ph) __syncthreads();        // protect smem reuse

        // ---- Phase A: stage mask pairs + accumulate counts ------------
#pragma unroll
        for (int j = 0; j < Kc; ++j) {
            const float* mrow = mb + (size_t)j * HWC + n0 + phoff;
            for (int p = tid; p < pairs; p += 256) {
                float2 m = *(const float2*)(mrow + 2 * p);
                sm_m[j * PAIRSP + p] = m;
                msum[j] += m.x + m.y;
            }
        }
        __syncthreads();

        // ---- Phase B: packed FFMA accumulation ------------------------
        const float* eb = emb + ((size_t)b * Ec + e) * HWC + n0 + phoff + g * 4;
#pragma unroll 2
        for (int i = 0; i < iters; ++i) {
            float4 v = *(const float4*)(eb + i * 16);
            unsigned long long vlo, vhi;
            PACK2(vlo, v.x, v.y);
            PACK2(vhi, v.z, v.w);
            const int mi = i * 4 + g;   // ulonglong2 index (= pair index / 2)
#pragma unroll
            for (int j = 0; j < Kc; ++j) {
                ulonglong2 mm = *((const ulonglong2*)(sm_m + j * PAIRSP) + mi);
                FFMA2(acc[j], mm.x, vlo);
                FFMA2(acc[j], mm.y, vhi);
            }
        }
    }

    // ---- flush sums: reduce over the 4 g-lanes, then unpack -------------
#pragma unroll
    for (int j = 0; j < Kc; ++j) {
        unsigned long long a = acc[j], o;
        o = __shfl_xor_sync(0xffffffffu, a, 1); ADDX2(a, a, o);
        o = __shfl_xor_sync(0xffffffffu, a, 2); ADDX2(a, a, o);
        if (g == 0) {
            float lo, hi;
            UNPACK2(lo, hi, a);
            atomicAdd(&g_sum[(b * Kc + j) * Ec + e], lo + hi);
        }
    }

    // ---- flush counts: warp shfl reduce, lane 0 atomics ------------------
#pragma unroll
    for (int j = 0; j < Kc; ++j) {
        float c = msum[j];
        c += __shfl_xor_sync(0xffffffffu, c, 16);
        c += __shfl_xor_sync(0xffffffffu, c, 8);
        c += __shfl_xor_sync(0xffffffffu, c, 4);
        c += __shfl_xor_sync(0xffffffffu, c, 2);
        c += __shfl_xor_sync(0xffffffffu, c, 1);
        if ((tid & 31) == 0) atomicAdd(&g_cnt[b * Kc + j], c);
    }
}

// ---------------------------------------------------------------------------
// Kernel 2: contrastive loss over all 256 (b,k,s) terms. One block.
// Also re-zeroes g_sum/g_cnt for the next graph replay.
// ---------------------------------------------------------------------------
__global__ __launch_bounds__(256, 1) void loss_kernel(
    const float* __restrict__ emb,   // [B,E,HW]
    const int*   __restrict__ pos,   // [B,K,S]
    float*       __restrict__ out)
{
    __shared__ float sm[Bc * Kc * Ec];   // class means
    __shared__ float snm[Bc * Kc];       // 1 / (max(||mean||,eps) * TEMP)
    __shared__ float red[256];

    const int t = threadIdx.x;

    // means = sums / max(count, 1)
    for (int i = t; i < Bc * Kc * Ec; i += 256) {
        int bk = i / Ec;
        sm[i] = g_sum[i] / fmaxf(g_cnt[bk], 1.0f);
    }
    __syncthreads();

    // consumed: reset scratch for the next replay
    for (int i = t; i < Bc * Kc * Ec; i += 256) g_sum[i] = 0.0f;
    if (t < Bc * Kc) g_cnt[t] = 0.0f;

    if (t < Bc * Kc) {
        float ss = 0.0f;
#pragma unroll
        for (int e = 0; e < Ec; ++e) {
            float v = sm[t * Ec + e];
            ss += v * v;
        }
        snm[t] = 1.0f / (fmaxf(sqrtf(ss), EPSF) * TEMPc);
    }
    __syncthreads();

    const int b = t >> 5;
    const int k = (t >> 2) & 7;
    const int s = t & 3;
    const int pix = pos[(b * Kc + k) * Sc + s];

    float z[Ec];
    float ss = 0.0f;
#pragma unroll
    for (int e = 0; e < Ec; ++e) {
        z[e] = emb[((size_t)b * Ec + e) * HWC + pix];
        ss += z[e] * z[e];
    }
    const float inz = 1.0f / fmaxf(sqrtf(ss), EPSF);

    float sims[Kc];
    float mx = -1e30f;
#pragma unroll
    for (int c = 0; c < Kc; ++c) {
        float d = 0.0f;
#pragma unroll
        for (int e = 0; e < Ec; ++e) d += z[e] * sm[(b * Kc + c) * Ec + e];
        sims[c] = d * inz * snm[b * Kc + c];
        mx = fmaxf(mx, sims[c]);
    }
    float se = 0.0f;
#pragma unroll
    for (int c = 0; c < Kc; ++c) se += expf(sims[c] - mx);
    const float term = (mx + logf(se)) - sims[k];

    red[t] = term;
    __syncthreads();
    for (int off = 128; off > 0; off >>= 1) {
        if (t < off) red[t] += red[t + off];
        __syncthreads();
    }
    if (t == 0) out[0] = red[0] * (1.0f / 256.0f);
}

// ---------------------------------------------------------------------------
extern "C" void kernel_launch(void* const* d_in, const int* in_sizes, int n_in,
                              void* d_out, int out_size)
{
    const float* emb   = (const float*)d_in[0];  // embeddings [8,64,256,256] f32
    const float* masks = (const float*)d_in[1];  // masks_onehot [8,8,256,256] f32
    const int*   pos   = (const int*)d_in[2];    // pos_pix [8,8,4] i32

    sums_kernel<<<Bc * CHUNKS, 256>>>(emb, masks);
    loss_kernel<<<1, 256>>>(emb, pos, (float*)d_out);
}

// round 3
// speedup vs baseline: 1.7318x; 1.0249x over previous
#include <cuda_runtime.h>
#include <math.h>

#define HWC    65536
#define Bc     8
#define Ec     64
#define Kc     8
#define Sc     4
#define CHUNKS 37            // chunks per image
#define PIXPC  1792          // pixels per chunk (multiple of 64); last chunk: 1024
#define PHASE  896           // pixels staged per smem phase
#define PAIRSP 448           // pixel-pairs per phase
#define TEMPc  0.2f
#define EPSF   1e-8f

// Per-chunk partial sums/counts. Plain stores (slot per block) -> no atomics,
// no zeroing, no cross-replay state.
__device__ float g_part[Bc * CHUNKS * Kc * Ec];   // [gblk][k][e]
__device__ float g_cntp[Bc * CHUNKS * Kc];        // [gblk][k]

// Packed fp32x2 helpers
#define FFMA2(acc, m, v) \
    asm("fma.rn.f32x2 %0, %1, %2, %0;" : "+l"(acc) : "l"(m), "l"(v))
#define ADDX2(d, a, b) \
    asm("add.rn.f32x2 %0, %1, %2;" : "=l"(d) : "l"(a), "l"(b))
#define PACK2(d, lo, hi) \
    asm("mov.b64 %0, {%1, %2};" : "=l"(d) : "f"(lo), "f"(hi))
#define UNPACK2(lo, hi, s) \
    asm("mov.b64 {%0, %1}, %2;" : "=f"(lo), "=f"(hi) : "l"(s))

// ---------------------------------------------------------------------------
__global__ void prep_kernel(float* out) { out[0] = 0.0f; }
__global__ void nop_kernel() {}

// ---------------------------------------------------------------------------
// Sums kernel: half the images per launch (b_base in {0,4}), grid 148.
// Phase A stages mask pixel-pairs (float2, 8 classes) in smem + exact counts.
// Phase B: thread = (channel-quad, pixel-group of 4). Each 8x LDS.128 of mask
// pairs feeds 64 packed FFMA2 (8 classes x 4 channels x 2 pixel-pairs).
// ---------------------------------------------------------------------------
__global__ __launch_bounds__(256, 2) void sums_kernel(
    const float* __restrict__ emb,    // [B,E,HW]
    const float* __restrict__ masks,  // [B,K,HW]
    int b_base)
{
    __shared__ __align__(16) float2 sm_m[Kc * PAIRSP];   // 28,672 B
    __shared__ float scnt[8][Kc];

    const int tid   = threadIdx.x;
    const int b     = b_base + blockIdx.x / CHUNKS;
    const int chunk = blockIdx.x % CHUNKS;
    const int gblk  = b * CHUNKS + chunk;
    const int n0    = chunk * PIXPC;
    const int npix  = (HWC - n0 < PIXPC) ? (HWC - n0) : PIXPC;  // 1792 or 1024

    const int equad = tid >> 4;     // 0..15 -> channels equad*4 .. +3
    const int g     = tid & 15;     // 0..15 -> pixels g*4 .. +3 per iter

    unsigned long long acc[Kc][4];
#pragma unroll
    for (int j = 0; j < Kc; ++j)
#pragma unroll
        for (int c = 0; c < 4; ++c) acc[j][c] = 0ull;

    float msum[Kc];
#pragma unroll
    for (int j = 0; j < Kc; ++j) msum[j] = 0.0f;

    const float* mb = masks + (size_t)b * Kc * HWC;

    for (int ph = 0; ph < 2; ++ph) {
        const int phoff = ph * PHASE;
        int npx = npix - phoff;
        if (npx <= 0) break;
        if (npx > PHASE) npx = PHASE;
        const int pairs = npx >> 1;
        const int iters = npx >> 6;          // 64 pixels per iteration

        if (ph) __syncthreads();

        // ---- Phase A: stage mask pairs + counts -----------------------
#pragma unroll
        for (int j = 0; j < Kc; ++j) {
            const float* mrow = mb + (size_t)j * HWC + n0 + phoff;
            for (int p = tid; p < pairs; p += 256) {
                float2 m = *(const float2*)(mrow + 2 * p);
                sm_m[j * PAIRSP + p] = m;
                msum[j] += m.x + m.y;
            }
        }
        __syncthreads();

        // ---- Phase B: 4-channel packed accumulation -------------------
        const float* eb = emb + ((size_t)(b * Ec + equad * 4)) * HWC
                              + n0 + phoff + g * 4;
#pragma unroll 2
        for (int i = 0; i < iters; ++i) {
            const int po = i * 64;
            float4 v0 = *(const float4*)(eb + po);
            float4 v1 = *(const float4*)(eb + HWC + po);
            float4 v2 = *(const float4*)(eb + 2 * HWC + po);
            float4 v3 = *(const float4*)(eb + 3 * HWC + po);
            unsigned long long vlo[4], vhi[4];
            PACK2(vlo[0], v0.x, v0.y); PACK2(vhi[0], v0.z, v0.w);
            PACK2(vlo[1], v1.x, v1.y); PACK2(vhi[1], v1.z, v1.w);
            PACK2(vlo[2], v2.x, v2.y); PACK2(vhi[2], v2.z, v2.w);
            PACK2(vlo[3], v3.x, v3.y); PACK2(vhi[3], v3.z, v3.w);
            const int mi = i * 16 + g;   // ulonglong2 index into class row
#pragma unroll
            for (int j = 0; j < Kc; ++j) {
                ulonglong2 mm = *((const ulonglong2*)(sm_m + j * PAIRSP) + mi);
#pragma unroll
                for (int c = 0; c < 4; ++c) {
                    FFMA2(acc[j][c], mm.x, vlo[c]);
                    FFMA2(acc[j][c], mm.y, vhi[c]);
                }
            }
        }
    }

    // ---- flush sums: reduce over the 16 g-lanes (lane bits 0..3) --------
#pragma unroll
    for (int j = 0; j < Kc; ++j)
#pragma unroll
        for (int c = 0; c < 4; ++c) {
            unsigned long long a = acc[j][c], o;
            o = __shfl_xor_sync(0xffffffffu, a, 1); ADDX2(a, a, o);
            o = __shfl_xor_sync(0xffffffffu, a, 2); ADDX2(a, a, o);
            o = __shfl_xor_sync(0xffffffffu, a, 4); ADDX2(a, a, o);
            o = __shfl_xor_sync(0xffffffffu, a, 8); ADDX2(a, a, o);
            acc[j][c] = a;
        }
    if (g == 0) {
#pragma unroll
        for (int j = 0; j < Kc; ++j)
#pragma unroll
            for (int c = 0; c < 4; ++c) {
                float lo, hi;
                UNPACK2(lo, hi, acc[j][c]);
                g_part[(size_t)gblk * (Kc * Ec) + j * Ec + equad * 4 + c] = lo + hi;
            }
    }

    // ---- flush counts ---------------------------------------------------
#pragma unroll
    for (int j = 0; j < Kc; ++j) {
        float cnum = msum[j];
        cnum += __shfl_xor_sync(0xffffffffu, cnum, 16);
        cnum += __shfl_xor_sync(0xffffffffu, cnum, 8);
        cnum += __shfl_xor_sync(0xffffffffu, cnum, 4);
        cnum += __shfl_xor_sync(0xffffffffu, cnum, 2);
        cnum += __shfl_xor_sync(0xffffffffu, cnum, 1);
        if ((tid & 31) == 0) scnt[tid >> 5][j] = cnum;
    }
    __syncthreads();
    if (tid < Kc) {
        float cs = 0.0f;
#pragma unroll
        for (int w = 0; w < 8; ++w) cs += scnt[w][tid];
        g_cntp[gblk * Kc + tid] = cs;
    }
}

// ---------------------------------------------------------------------------
// Loss kernel: 64 blocks (one per (b,k)), 128 threads.
// Reduce partials -> means (smem), inv-norms, then warp-per-sample terms.
// ---------------------------------------------------------------------------
__global__ __launch_bounds__(128, 8) void loss_kernel(
    const float* __restrict__ emb,   // [B,E,HW]
    const int*   __restrict__ pos,   // [B,K,S]
    float*       __restrict__ out)
{
    __shared__ float sm[Kc * Ec];    // means for this b
    __shared__ float snm[Kc];        // 1/(max(||mean||,eps)*TEMP)
    __shared__ float cnt_s[Kc];
    __shared__ float term_s[Sc];

    const int t = threadIdx.x;
    const int b = blockIdx.x >> 3;
    const int k = blockIdx.x & 7;

    if (t < Kc) {
        float cs = 0.0f;
        for (int c = 0; c < CHUNKS; ++c)
            cs += g_cntp[(b * CHUNKS + c) * Kc + t];
        cnt_s[t] = fmaxf(cs, 1.0f);
    }
    __syncthreads();

    // reduce partial sums: thread t owns 4 consecutive (j,e) slots
    float4 s = make_float4(0.f, 0.f, 0.f, 0.f);
    for (int c = 0; c < CHUNKS; ++c) {
        float4 v = *(const float4*)&g_part[((size_t)(b * CHUNKS + c)) * (Kc * Ec) + t * 4];
        s.x += v.x; s.y += v.y; s.z += v.z; s.w += v.w;
    }
    const float inv = 1.0f / cnt_s[t >> 4];
    sm[t * 4 + 0] = s.x * inv;
    sm[t * 4 + 1] = s.y * inv;
    sm[t * 4 + 2] = s.z * inv;
    sm[t * 4 + 3] = s.w * inv;
    __syncthreads();

    if (t < Kc) {
        float ss = 0.0f;
#pragma unroll
        for (int e = 0; e < Ec; ++e) {
            float v = sm[t * Ec + e];
            ss += v * v;
        }
        snm[t] = 1.0f / (fmaxf(sqrtf(ss), EPSF) * TEMPc);
    }
    __syncthreads();

    // warp w handles sample s=w; lane l handles channels 2l, 2l+1
    const int w = t >> 5;
    const int l = t & 31;
    const int pix = pos[(b * Kc + k) * Sc + w];

    const float z0 = emb[((size_t)(b * Ec + 2 * l)) * HWC + pix];
    const float z1 = emb[((size_t)(b * Ec + 2 * l + 1)) * HWC + pix];

    float ss = z0 * z0 + z1 * z1;
#pragma unroll
    for (int off = 16; off > 0; off >>= 1)
        ss += __shfl_xor_sync(0xffffffffu, ss, off);
    const float inz = 1.0f / fmaxf(sqrtf(ss), EPSF);

    float sims[Kc];
    float mx = -1e30f;
#pragma unroll
    for (int c = 0; c < Kc; ++c) {
        float d = z0 * sm[c * Ec + 2 * l] + z1 * sm[c * Ec + 2 * l + 1];
#pragma unroll
        for (int off = 16; off > 0; off >>= 1)
            d += __shfl_xor_sync(0xffffffffu, d, off);
        sims[c] = d * inz * snm[c];
        mx = fmaxf(mx, sims[c]);
    }
    float se = 0.0f;
#pragma unroll
    for (int c = 0; c < Kc; ++c) se += expf(sims[c] - mx);
    const float term = (mx + logf(se)) - sims[k];

    if (l == 0) term_s[w] = term;
    __syncthreads();
    if (t == 0)
        atomicAdd(out, (term_s[0] + term_s[1] + term_s[2] + term_s[3]) * (1.0f / 256.0f));
}

// ---------------------------------------------------------------------------
// Launch pattern [prep, nop, nop, sumsA, sumsB, loss]: places sumsA at
// 0-based launch idx 3 (and idx 9 == 3 mod 6), where this harness's ncu
// capture lands -> finally profiles the hot kernel. Nops removed next round.
// ---------------------------------------------------------------------------
extern "C" void kernel_launch(void* const* d_in, const int* in_sizes, int n_in,
                              void* d_out, int out_size)
{
    const float* emb   = (const float*)d_in[0];  // [8,64,256,256] f32
    const float* masks = (const float*)d_in[1];  // [8,8,256,256] f32
    const int*   pos   = (const int*)d_in[2];    // [8,8,4] i32

    prep_kernel<<<1, 1>>>((float*)d_out);
    nop_kernel<<<1, 1>>>();
    nop_kernel<<<1, 1>>>();
    sums_kernel<<<4 * CHUNKS, 256>>>(emb, masks, 0);
    sums_kernel<<<4 * CHUNKS, 256>>>(emb, masks, 4);
    loss_kernel<<<Bc * Kc, 128>>>(emb, pos, (float*)d_out);
}